// round 2
// baseline (speedup 1.0000x reference)
#include <cuda_runtime.h>
#include <math.h>

// Problem constants
#define B_    512
#define H_    512
#define OUT_  66
#define NCLS_ 12
#define INW_  78            // OUT_ + NCLS_
#define G4_   2048          // 4*H_
#define LEN_  64
#define BH_   (B_*H_)       // 262144

// Device scratch (no allocations allowed)
__device__ float g_Wt1[H_ * G4_];       // W_hh^T            [K=512][N=2048]
__device__ float g_Wt2[H_ * G4_];       // (W_hh + Wio@Wfc)^T
__device__ float g_Z0[B_ * G4_];        // step-0 additive term
__device__ float g_Z [B_ * G4_];        // steps>=1 additive term
__device__ float g_h0[BH_];
__device__ float g_c [BH_];
__device__ float g_G [B_ * G4_];        // gates buffer
__device__ float g_H [LEN_ * BH_];      // all hidden states (64 MB)

__device__ __forceinline__ float sigm(float x) { return 1.0f / (1.0f + expf(-x)); }

// ---------------------------------------------------------------------------
// h0 = frame0 @ W_inh^T + b_inh ; c0 = frame0 @ W_inc^T + b_inc
// one block per batch row
// ---------------------------------------------------------------------------
__global__ void k_prep_state(const float* __restrict__ inp,
                             const float* __restrict__ Winh, const float* __restrict__ binh,
                             const float* __restrict__ Winc, const float* __restrict__ binc) {
    int b = blockIdx.x;
    __shared__ float fr[OUT_];
    if (threadIdx.x < OUT_) fr[threadIdx.x] = inp[b * OUT_ + threadIdx.x];
    __syncthreads();
    for (int k = threadIdx.x; k < H_; k += blockDim.x) {
        float sh = binh[k], sc = binc[k];
        const float* wh = Winh + k * OUT_;
        const float* wc = Winc + k * OUT_;
        #pragma unroll 6
        for (int j = 0; j < OUT_; j++) {
            float f = fr[j];
            sh += f * wh[j];
            sc += f * wc[j];
        }
        g_h0[b * H_ + k] = sh;
        g_c [b * H_ + k] = sc;
    }
}

// ---------------------------------------------------------------------------
// Z0[b,n] = b_ih+b_hh + W_ih[n,66+lbl] + sum_j frame0[b,j]*W_ih[n,j]
// Z [b,n] = b_ih+b_hh + W_ih[n,66+lbl] + sum_j b_fc[j]   *W_ih[n,j]
// grid (8 n-blocks, 64 b-blocks of 8)
// ---------------------------------------------------------------------------
__global__ void k_prep_Z(const float* __restrict__ W_ih,
                         const float* __restrict__ b_ih, const float* __restrict__ b_hh,
                         const float* __restrict__ b_fc,
                         const float* __restrict__ inp, const int* __restrict__ labels) {
    int n  = blockIdx.x * 256 + threadIdx.x;
    int bb = blockIdx.y * 8;
    __shared__ float fr[8][OUT_];
    __shared__ float bf[OUT_];
    __shared__ int   lb[8];
    for (int x = threadIdx.x; x < 8 * OUT_; x += 256)
        fr[x / OUT_][x % OUT_] = inp[(bb + x / OUT_) * OUT_ + (x % OUT_)];
    if (threadIdx.x < OUT_) bf[threadIdx.x] = b_fc[threadIdx.x];
    if (threadIdx.x < 8)    lb[threadIdx.x] = labels[bb + threadIdx.x];
    __syncthreads();

    const float* w = W_ih + (size_t)n * INW_;
    float s1 = 0.0f;
    float a[8] = {0, 0, 0, 0, 0, 0, 0, 0};
    #pragma unroll 6
    for (int j = 0; j < OUT_; j++) {
        float wj = w[j];
        s1 += bf[j] * wj;
        #pragma unroll
        for (int i = 0; i < 8; i++) a[i] += fr[i][j] * wj;
    }
    float base = b_ih[n] + b_hh[n];
    #pragma unroll
    for (int i = 0; i < 8; i++) {
        int b = bb + i;
        float cls = w[OUT_ + lb[i]];
        g_Z0[(size_t)b * G4_ + n] = base + cls + a[i];
        g_Z [(size_t)b * G4_ + n] = base + cls + s1;
    }
}

// ---------------------------------------------------------------------------
// Wt1[k,n] = W_hh[n,k] ; Wt2[k,n] = W_hh[n,k] + sum_j W_ih[n,j]*W_fc[j,k]
// grid (8 n-blocks, 64 k-blocks of 8)
// ---------------------------------------------------------------------------
__global__ void k_prep_W(const float* __restrict__ W_ih,
                         const float* __restrict__ W_hh,
                         const float* __restrict__ W_fc) {
    int n  = blockIdx.x * 256 + threadIdx.x;
    int k0 = blockIdx.y * 8;
    __shared__ float wf[OUT_][8];
    for (int x = threadIdx.x; x < OUT_ * 8; x += 256)
        wf[x / 8][x % 8] = W_fc[(size_t)(x / 8) * H_ + k0 + (x % 8)];
    __syncthreads();

    const float* w = W_ih + (size_t)n * INW_;
    float a[8] = {0, 0, 0, 0, 0, 0, 0, 0};
    #pragma unroll 6
    for (int j = 0; j < OUT_; j++) {
        float wj = w[j];
        #pragma unroll
        for (int i = 0; i < 8; i++) a[i] += wj * wf[j][i];
    }
    #pragma unroll
    for (int i = 0; i < 8; i++) {
        int k = k0 + i;
        float whh = W_hh[(size_t)n * H_ + k];
        g_Wt1[(size_t)k * G4_ + n] = whh;
        g_Wt2[(size_t)k * G4_ + n] = whh + a[i];
    }
}

// ---------------------------------------------------------------------------
// Per-step GEMM: G[512,2048] = Hin[512,512] @ Wt[512,2048] + Z
// Tiles: BM=64, BN=128, BK=16; 256 threads, 4x8 per thread; reg-prefetch pipeline.
// grid (16, 8) = 128 CTAs.
// ---------------------------------------------------------------------------
__global__ __launch_bounds__(256) void k_gemm_step(int t) {
    const float* __restrict__ Hin = (t == 0) ? g_h0 : g_H + (size_t)(t - 1) * BH_;
    const float* __restrict__ W   = (t == 0) ? g_Wt1 : g_Wt2;
    const float* __restrict__ Z   = (t == 0) ? g_Z0  : g_Z;

    __shared__ float As[16][68];    // [k][m], padded to 68 for bank spread (16B aligned)
    __shared__ float Bs[16][128];   // [k][n]

    int tid = threadIdx.x;
    int tx = tid & 15;              // n-direction (8 cols each)
    int ty = tid >> 4;              // m-direction (4 rows each)
    int n0 = blockIdx.x * 128;
    int m0 = blockIdx.y * 64;

    // A staging indices: one float4 along k per thread
    int am = tid >> 2;
    int ak = (tid & 3) << 2;
    // B staging indices: two float4 along n per thread
    int b1r = tid >> 5;
    int b1c = (tid & 31) << 2;
    int b2r = b1r + 8;

    float acc[4][8];
    {
        const float* zp = Z + (size_t)(m0 + ty * 4) * G4_ + n0 + tx * 8;
        #pragma unroll
        for (int i = 0; i < 4; i++) {
            float4 z0 = *(const float4*)(zp + (size_t)i * G4_);
            float4 z1 = *(const float4*)(zp + (size_t)i * G4_ + 4);
            acc[i][0] = z0.x; acc[i][1] = z0.y; acc[i][2] = z0.z; acc[i][3] = z0.w;
            acc[i][4] = z1.x; acc[i][5] = z1.y; acc[i][6] = z1.z; acc[i][7] = z1.w;
        }
    }

    const float* aptr  = Hin + (size_t)(m0 + am) * H_ + ak;
    const float* bptr1 = W + (size_t)b1r * G4_ + n0 + b1c;
    const float* bptr2 = W + (size_t)b2r * G4_ + n0 + b1c;

    float4 av  = *(const float4*)(aptr);
    float4 bv1 = *(const float4*)(bptr1);
    float4 bv2 = *(const float4*)(bptr2);

    for (int k0 = 0; k0 < H_; k0 += 16) {
        As[ak + 0][am] = av.x;
        As[ak + 1][am] = av.y;
        As[ak + 2][am] = av.z;
        As[ak + 3][am] = av.w;
        *(float4*)&Bs[b1r][b1c] = bv1;
        *(float4*)&Bs[b2r][b1c] = bv2;
        __syncthreads();

        if (k0 + 16 < H_) {
            av  = *(const float4*)(aptr + k0 + 16);
            bv1 = *(const float4*)(bptr1 + (size_t)(k0 + 16) * G4_);
            bv2 = *(const float4*)(bptr2 + (size_t)(k0 + 16) * G4_);
        }

        #pragma unroll
        for (int kk = 0; kk < 16; kk++) {
            float4 a  = *(const float4*)&As[kk][ty << 2];
            float4 b0 = *(const float4*)&Bs[kk][tx << 3];
            float4 b1 = *(const float4*)&Bs[kk][(tx << 3) + 4];
            float ar[4] = {a.x, a.y, a.z, a.w};
            float br[8] = {b0.x, b0.y, b0.z, b0.w, b1.x, b1.y, b1.z, b1.w};
            #pragma unroll
            for (int i = 0; i < 4; i++)
                #pragma unroll
                for (int j = 0; j < 8; j++)
                    acc[i][j] += ar[i] * br[j];
        }
        __syncthreads();
    }

    float* gp = g_G + (size_t)(m0 + ty * 4) * G4_ + n0 + tx * 8;
    #pragma unroll
    for (int i = 0; i < 4; i++) {
        float4 o0 = make_float4(acc[i][0], acc[i][1], acc[i][2], acc[i][3]);
        float4 o1 = make_float4(acc[i][4], acc[i][5], acc[i][6], acc[i][7]);
        *(float4*)(gp + (size_t)i * G4_)     = o0;
        *(float4*)(gp + (size_t)i * G4_ + 4) = o1;
    }
}

// ---------------------------------------------------------------------------
// LSTM pointwise: consumes gates G, updates c in-place, writes h into g_H[t]
// ---------------------------------------------------------------------------
__global__ void k_pointwise(int t) {
    int idx = blockIdx.x * blockDim.x + threadIdx.x;   // 0..BH_-1
    int b = idx >> 9;
    int u = idx & 511;
    const float* Gp = g_G + (size_t)b * G4_;
    float gi = Gp[u];
    float gf = Gp[512 + u];
    float gg = Gp[1024 + u];
    float go = Gp[1536 + u];
    float c  = g_c[idx];
    float cn = sigm(gf) * c + sigm(gi) * tanhf(gg);
    float hn = sigm(go) * tanhf(cn);
    g_c[idx] = cn;
    g_H[(size_t)t * BH_ + idx] = hn;
}

// ---------------------------------------------------------------------------
// Final: out[b,t,:] = g_H[t,b,:] @ W_fc^T + b_fc.   Warp per (t,b) row.
// ---------------------------------------------------------------------------
__global__ __launch_bounds__(256) void k_fc(float* __restrict__ out,
                                            const float* __restrict__ W_fc,
                                            const float* __restrict__ b_fc) {
    __shared__ float hs[8][H_];
    int w = threadIdx.x >> 5;
    int lane = threadIdx.x & 31;
    int r = blockIdx.x * 8 + w;                 // 0..32767  (r = t*512 + b)
    const float4* hrow = (const float4*)(g_H + (size_t)r * H_);
    float4* dst = (float4*)hs[w];
    #pragma unroll
    for (int x = lane; x < H_ / 4; x += 32) dst[x] = hrow[x];
    __syncwarp();

    int t = r >> 9;
    int b = r & 511;
    float* orow = out + ((size_t)b * LEN_ + t) * OUT_;
    const float4* hv = (const float4*)hs[w];
    for (int j = lane; j < OUT_; j += 32) {
        const float4* wrow = (const float4*)(W_fc + (size_t)j * H_);
        float s = 0.0f;
        #pragma unroll 8
        for (int x = 0; x < H_ / 4; x++) {
            float4 a = hv[x];
            float4 c = wrow[x];
            s += a.x * c.x + a.y * c.y + a.z * c.z + a.w * c.w;
        }
        orow[j] = s + b_fc[j];
    }
}

// ---------------------------------------------------------------------------
extern "C" void kernel_launch(void* const* d_in, const int* in_sizes, int n_in,
                              void* d_out, int out_size) {
    // metadata order: inputs, labels, [length], W_ih, W_hh, b_ih, b_hh,
    //                 W_fc, b_fc, W_inh, b_inh, W_inc, b_inc
    int off = (n_in >= 13) ? 1 : 0;   // 'length' scalar present
    const float* inputs = (const float*)d_in[0];
    const int*   labels = (const int*)  d_in[1];
    const float* W_ih  = (const float*)d_in[2 + off];
    const float* W_hh  = (const float*)d_in[3 + off];
    const float* b_ih  = (const float*)d_in[4 + off];
    const float* b_hh  = (const float*)d_in[5 + off];
    const float* W_fc  = (const float*)d_in[6 + off];
    const float* b_fc  = (const float*)d_in[7 + off];
    const float* W_inh = (const float*)d_in[8 + off];
    const float* b_inh = (const float*)d_in[9 + off];
    const float* W_inc = (const float*)d_in[10 + off];
    const float* b_inc = (const float*)d_in[11 + off];
    float* out = (float*)d_out;

    k_prep_state<<<B_, 256>>>(inputs, W_inh, b_inh, W_inc, b_inc);
    k_prep_Z<<<dim3(8, 64), 256>>>(W_ih, b_ih, b_hh, b_fc, inputs, labels);
    k_prep_W<<<dim3(8, 64), 256>>>(W_ih, W_hh, W_fc);

    for (int t = 0; t < LEN_; t++) {
        k_gemm_step<<<dim3(16, 8), 256>>>(t);
        k_pointwise<<<BH_ / 256, 256>>>(t);
    }

    k_fc<<<(LEN_ * B_) / 8, 256>>>(out, W_fc, b_fc);
}

// round 3
// speedup vs baseline: 1.2662x; 1.2662x over previous
#include <cuda_runtime.h>
#include <math.h>

// Problem constants
#define B_    512
#define H_    512
#define OUT_  66
#define NCLS_ 12
#define INW_  78            // OUT_ + NCLS_
#define G4_   2048          // 4*H_
#define LEN_  64
#define BH_   (B_*H_)       // 262144

// Device scratch (no allocations allowed)
// Weight/Z columns are PERMUTED: p = u*4 + gate  (gate order i,f,g,o), u=0..511
__device__ float g_Wt1[H_ * G4_];       // W_hh^T permuted          [K=512][N'=2048]
__device__ float g_Wt2[H_ * G4_];       // (W_hh + Wio@Wfc)^T permuted
__device__ float g_Z0[B_ * G4_];        // step-0 additive term (permuted cols)
__device__ float g_Z [B_ * G4_];        // steps>=1 additive term (permuted cols)
__device__ float g_h0[BH_];
__device__ float g_c [BH_];
__device__ float g_H [LEN_ * BH_];      // all hidden states (64 MB)

__device__ __forceinline__ float sigm(float x) { return 1.0f / (1.0f + expf(-x)); }

// packed f32x2 helpers (sm_100+)
__device__ __forceinline__ void ffma2(unsigned long long& d, unsigned long long a,
                                      unsigned long long b) {
    asm("fma.rn.f32x2 %0, %1, %2, %0;" : "+l"(d) : "l"(a), "l"(b));
}
__device__ __forceinline__ unsigned long long splat2(float x) {
    unsigned long long r;
    asm("mov.b64 %0, {%1, %1};" : "=l"(r) : "f"(x));
    return r;
}
__device__ __forceinline__ unsigned long long pack2(float lo, float hi) {
    unsigned long long r;
    asm("mov.b64 %0, {%1, %2};" : "=l"(r) : "f"(lo), "f"(hi));
    return r;
}
__device__ __forceinline__ float2 unpack2(unsigned long long v) {
    float2 f;
    asm("mov.b64 {%0, %1}, %2;" : "=f"(f.x), "=f"(f.y) : "l"(v));
    return f;
}

// ---------------------------------------------------------------------------
// h0 = frame0 @ W_inh^T + b_inh ; c0 = frame0 @ W_inc^T + b_inc
// ---------------------------------------------------------------------------
__global__ void k_prep_state(const float* __restrict__ inp,
                             const float* __restrict__ Winh, const float* __restrict__ binh,
                             const float* __restrict__ Winc, const float* __restrict__ binc) {
    int b = blockIdx.x;
    __shared__ float fr[OUT_];
    if (threadIdx.x < OUT_) fr[threadIdx.x] = inp[b * OUT_ + threadIdx.x];
    __syncthreads();
    for (int k = threadIdx.x; k < H_; k += blockDim.x) {
        float sh = binh[k], sc = binc[k];
        const float* wh = Winh + k * OUT_;
        const float* wc = Winc + k * OUT_;
        #pragma unroll 6
        for (int j = 0; j < OUT_; j++) {
            float f = fr[j];
            sh += f * wh[j];
            sc += f * wc[j];
        }
        g_h0[b * H_ + k] = sh;
        g_c [b * H_ + k] = sc;
    }
}

// ---------------------------------------------------------------------------
// Z (permuted columns p = u*4+gate):
// Z0[b,p(n)] = b_ih+b_hh + W_ih[n,66+lbl] + sum_j frame0[b,j]*W_ih[n,j]
// Z [b,p(n)] = b_ih+b_hh + W_ih[n,66+lbl] + sum_j b_fc[j]   *W_ih[n,j]
// ---------------------------------------------------------------------------
__global__ void k_prep_Z(const float* __restrict__ W_ih,
                         const float* __restrict__ b_ih, const float* __restrict__ b_hh,
                         const float* __restrict__ b_fc,
                         const float* __restrict__ inp, const int* __restrict__ labels) {
    int n  = blockIdx.x * 256 + threadIdx.x;        // original column
    int p  = ((n & 511) << 2) | (n >> 9);           // permuted column
    int bb = blockIdx.y * 8;
    __shared__ float fr[8][OUT_];
    __shared__ float bf[OUT_];
    __shared__ int   lb[8];
    for (int x = threadIdx.x; x < 8 * OUT_; x += 256)
        fr[x / OUT_][x % OUT_] = inp[(bb + x / OUT_) * OUT_ + (x % OUT_)];
    if (threadIdx.x < OUT_) bf[threadIdx.x] = b_fc[threadIdx.x];
    if (threadIdx.x < 8)    lb[threadIdx.x] = labels[bb + threadIdx.x];
    __syncthreads();

    const float* w = W_ih + (size_t)n * INW_;
    float s1 = 0.0f;
    float a[8] = {0, 0, 0, 0, 0, 0, 0, 0};
    #pragma unroll 6
    for (int j = 0; j < OUT_; j++) {
        float wj = w[j];
        s1 += bf[j] * wj;
        #pragma unroll
        for (int i = 0; i < 8; i++) a[i] += fr[i][j] * wj;
    }
    float base = b_ih[n] + b_hh[n];
    #pragma unroll
    for (int i = 0; i < 8; i++) {
        int b = bb + i;
        float cls = w[OUT_ + lb[i]];
        g_Z0[(size_t)b * G4_ + p] = base + cls + a[i];
        g_Z [(size_t)b * G4_ + p] = base + cls + s1;
    }
}

// ---------------------------------------------------------------------------
// Wt1[k,p(n)] = W_hh[n,k] ; Wt2[k,p(n)] = W_hh[n,k] + sum_j W_ih[n,j]*W_fc[j,k]
// ---------------------------------------------------------------------------
__global__ void k_prep_W(const float* __restrict__ W_ih,
                         const float* __restrict__ W_hh,
                         const float* __restrict__ W_fc) {
    int n  = blockIdx.x * 256 + threadIdx.x;
    int p  = ((n & 511) << 2) | (n >> 9);
    int k0 = blockIdx.y * 8;
    __shared__ float wf[OUT_][8];
    for (int x = threadIdx.x; x < OUT_ * 8; x += 256)
        wf[x / 8][x % 8] = W_fc[(size_t)(x / 8) * H_ + k0 + (x % 8)];
    __syncthreads();

    const float* w = W_ih + (size_t)n * INW_;
    float a[8] = {0, 0, 0, 0, 0, 0, 0, 0};
    #pragma unroll 6
    for (int j = 0; j < OUT_; j++) {
        float wj = w[j];
        #pragma unroll
        for (int i = 0; i < 8; i++) a[i] += wj * wf[j][i];
    }
    #pragma unroll
    for (int i = 0; i < 8; i++) {
        int k = k0 + i;
        float whh = W_hh[(size_t)n * H_ + k];
        g_Wt1[(size_t)k * G4_ + p] = whh;
        g_Wt2[(size_t)k * G4_ + p] = whh + a[i];
    }
}

// ---------------------------------------------------------------------------
// Fused step: gates = Hin @ Wt + Z (permuted cols), then LSTM pointwise.
// Tiles: BM=64, BN=64 (=16 u x 4 gates), BK=16. 256 threads, 4m x 4n each
// (f32x2 packed FMA: m-pairs in lanes). Double-buffered smem, 1 sync/slab.
// grid (32, 8) = 256 CTAs -> 2 CTAs/SM.
// ---------------------------------------------------------------------------
__global__ __launch_bounds__(256) void k_step(int t) {
    const float* __restrict__ Hin = (t == 0) ? g_h0 : g_H + (size_t)(t - 1) * BH_;
    const float* __restrict__ W   = (t == 0) ? g_Wt1 : g_Wt2;
    const float* __restrict__ Z   = (t == 0) ? g_Z0  : g_Z;

    __shared__ __align__(16) float As[2][16][68];   // [k][m] padded
    __shared__ __align__(16) float Bs[2][16][64];   // [k][n]

    int tid = threadIdx.x;
    int tx = tid & 15;              // n dir: 4 cols each (one u, 4 gates)
    int ty = tid >> 4;              // m dir: 4 rows each
    int n0 = blockIdx.x * 64;
    int m0 = blockIdx.y * 64;

    // staging indices
    int am = tid >> 2;              // 64 rows
    int ak = (tid & 3) << 2;        // 4 k-float4 per row
    int br = tid >> 4;              // 16 k rows
    int bc = (tid & 15) << 2;       // 64 n cols

    // acc2[j][p]: gate-col j (i,f,g,o), m-pair p; lanes = (m0+ty*4+2p, +1)
    unsigned long long acc2[4][2];
    {
        const float* zp = Z + (size_t)(m0 + ty * 4) * G4_ + n0 + tx * 4;
        #pragma unroll
        for (int p = 0; p < 2; p++) {
            float4 za = *(const float4*)(zp + (size_t)(2 * p)     * G4_);
            float4 zb = *(const float4*)(zp + (size_t)(2 * p + 1) * G4_);
            acc2[0][p] = pack2(za.x, zb.x);
            acc2[1][p] = pack2(za.y, zb.y);
            acc2[2][p] = pack2(za.z, zb.z);
            acc2[3][p] = pack2(za.w, zb.w);
        }
    }

    const float* aptr = Hin + (size_t)(m0 + am) * H_ + ak;
    const float* bptr = W + (size_t)br * G4_ + n0 + bc;

    float4 av = *(const float4*)(aptr);
    float4 bv = *(const float4*)(bptr);
    As[0][ak + 0][am] = av.x;
    As[0][ak + 1][am] = av.y;
    As[0][ak + 2][am] = av.z;
    As[0][ak + 3][am] = av.w;
    *(float4*)&Bs[0][br][bc] = bv;
    __syncthreads();

    #pragma unroll 1
    for (int i = 0; i < 32; i++) {
        int s = i & 1;
        if (i < 31) {
            av = *(const float4*)(aptr + (i + 1) * 16);
            bv = *(const float4*)(bptr + (size_t)(i + 1) * 16 * G4_);
        }
        #pragma unroll
        for (int kk = 0; kk < 16; kk++) {
            ulonglong2 ap = *(const ulonglong2*)&As[s][kk][ty << 2]; // (m0,m1),(m2,m3)
            float4 b = *(const float4*)&Bs[s][kk][tx << 2];
            unsigned long long bs0 = splat2(b.x);
            unsigned long long bs1 = splat2(b.y);
            unsigned long long bs2 = splat2(b.z);
            unsigned long long bs3 = splat2(b.w);
            ffma2(acc2[0][0], ap.x, bs0); ffma2(acc2[0][1], ap.y, bs0);
            ffma2(acc2[1][0], ap.x, bs1); ffma2(acc2[1][1], ap.y, bs1);
            ffma2(acc2[2][0], ap.x, bs2); ffma2(acc2[2][1], ap.y, bs2);
            ffma2(acc2[3][0], ap.x, bs3); ffma2(acc2[3][1], ap.y, bs3);
        }
        if (i < 31) {
            int d = s ^ 1;
            As[d][ak + 0][am] = av.x;
            As[d][ak + 1][am] = av.y;
            As[d][ak + 2][am] = av.z;
            As[d][ak + 3][am] = av.w;
            *(float4*)&Bs[d][br][bc] = bv;
        }
        __syncthreads();
    }

    // Fused LSTM pointwise epilogue
    int u = (blockIdx.x << 4) + tx;
    float* hout = g_H + (size_t)t * BH_;
    #pragma unroll
    for (int p = 0; p < 2; p++) {
        float2 gI = unpack2(acc2[0][p]);
        float2 gF = unpack2(acc2[1][p]);
        float2 gG = unpack2(acc2[2][p]);
        float2 gO = unpack2(acc2[3][p]);
        #pragma unroll
        for (int h = 0; h < 2; h++) {
            int b = m0 + ty * 4 + 2 * p + h;
            float gi = h ? gI.y : gI.x;
            float gf = h ? gF.y : gF.x;
            float gg = h ? gG.y : gG.x;
            float go = h ? gO.y : gO.x;
            int idx = b * H_ + u;
            float c  = g_c[idx];
            float cn = sigm(gf) * c + sigm(gi) * tanhf(gg);
            float hn = sigm(go) * tanhf(cn);
            g_c[idx] = cn;
            hout[idx] = hn;
        }
    }
}

// ---------------------------------------------------------------------------
// Final: out[b,t,:] = g_H[t,b,:] @ W_fc^T + b_fc.   Warp per (t,b) row.
// ---------------------------------------------------------------------------
__global__ __launch_bounds__(256) void k_fc(float* __restrict__ out,
                                            const float* __restrict__ W_fc,
                                            const float* __restrict__ b_fc) {
    __shared__ float hs[8][H_];
    int w = threadIdx.x >> 5;
    int lane = threadIdx.x & 31;
    int r = blockIdx.x * 8 + w;                 // r = t*512 + b
    const float4* hrow = (const float4*)(g_H + (size_t)r * H_);
    float4* dst = (float4*)hs[w];
    #pragma unroll
    for (int x = lane; x < H_ / 4; x += 32) dst[x] = hrow[x];
    __syncwarp();

    int t = r >> 9;
    int b = r & 511;
    float* orow = out + ((size_t)b * LEN_ + t) * OUT_;
    const float4* hv = (const float4*)hs[w];
    for (int j = lane; j < OUT_; j += 32) {
        const float4* wrow = (const float4*)(W_fc + (size_t)j * H_);
        float s = 0.0f;
        #pragma unroll 8
        for (int x = 0; x < H_ / 4; x++) {
            float4 a = hv[x];
            float4 c = wrow[x];
            s += a.x * c.x + a.y * c.y + a.z * c.z + a.w * c.w;
        }
        orow[j] = s + b_fc[j];
    }
}

// ---------------------------------------------------------------------------
extern "C" void kernel_launch(void* const* d_in, const int* in_sizes, int n_in,
                              void* d_out, int out_size) {
    int off = (n_in >= 13) ? 1 : 0;   // 'length' scalar present
    const float* inputs = (const float*)d_in[0];
    const int*   labels = (const int*)  d_in[1];
    const float* W_ih  = (const float*)d_in[2 + off];
    const float* W_hh  = (const float*)d_in[3 + off];
    const float* b_ih  = (const float*)d_in[4 + off];
    const float* b_hh  = (const float*)d_in[5 + off];
    const float* W_fc  = (const float*)d_in[6 + off];
    const float* b_fc  = (const float*)d_in[7 + off];
    const float* W_inh = (const float*)d_in[8 + off];
    const float* b_inh = (const float*)d_in[9 + off];
    const float* W_inc = (const float*)d_in[10 + off];
    const float* b_inc = (const float*)d_in[11 + off];
    float* out = (float*)d_out;

    k_prep_state<<<B_, 256>>>(inputs, W_inh, b_inh, W_inc, b_inc);
    k_prep_Z<<<dim3(8, 64), 256>>>(W_ih, b_ih, b_hh, b_fc, inputs, labels);
    k_prep_W<<<dim3(8, 64), 256>>>(W_ih, W_hh, W_fc);

    for (int t = 0; t < LEN_; t++) {
        k_step<<<dim3(32, 8), 256>>>(t);
    }

    k_fc<<<(LEN_ * B_) / 8, 256>>>(out, W_fc, b_fc);
}